// round 6
// baseline (speedup 1.0000x reference)
#include <cuda_runtime.h>
#include <math.h>

#define DIM 768
#define HEADS 12
#define HD 64
#define HIDDEN 3072
#define BATCH 16
#define N_SEQ 1024
#define TOK (BATCH * N_SEQ)

typedef unsigned long long ull;

// scratch: no allocations allowed -> __device__ globals
__device__ float g_xn1[(size_t)TOK * DIM];
__device__ float g_qkv[(size_t)TOK * 3 * DIM];
__device__ float g_ctx[(size_t)TOK * DIM];
__device__ float g_xa[(size_t)TOK * DIM];
__device__ float g_ffin[(size_t)TOK * DIM];
__device__ float g_h[(size_t)TOK * HIDDEN];
__device__ float g_xm[(size_t)TOK * DIM];

// packed f32x2 helpers (Blackwell FFMA2 path)
__device__ __forceinline__ ull pack2(float x) {
    ull r; asm("mov.b64 %0, {%1, %1};" : "=l"(r) : "f"(x)); return r;
}
__device__ __forceinline__ ull pack2(float x, float y) {
    ull r; asm("mov.b64 %0, {%1, %2};" : "=l"(r) : "f"(x), "f"(y)); return r;
}
__device__ __forceinline__ float2 unpack2(ull v) {
    float2 f; asm("mov.b64 {%0, %1}, %2;" : "=f"(f.x), "=f"(f.y) : "l"(v)); return f;
}
__device__ __forceinline__ void fma2(ull& c, ull a, ull b) {
    asm("fma.rn.f32x2 %0, %1, %2, %0;" : "+l"(c) : "l"(a), "l"(b));
}
__device__ __forceinline__ void mul2(ull& c, ull a) {
    asm("mul.rn.f32x2 %0, %0, %1;" : "+l"(c) : "l"(a));
}
__device__ __forceinline__ float gelu_f(float x) {
    return 0.5f * x * (1.0f + erff(x * 0.70710678118654752440f));
}

// ---------------- LayerNorm: one 256-thread block per token row -------------
__global__ void __launch_bounds__(256) ln_kernel(const float* __restrict__ x,
                                                 const float* __restrict__ gw,
                                                 const float* __restrict__ bw,
                                                 float* __restrict__ out)
{
    __shared__ float red[2][8];
    int row = blockIdx.x, tid = threadIdx.x;
    const float* xr = x + (size_t)row * DIM;
    float v0 = xr[tid], v1 = xr[tid + 256], v2 = xr[tid + 512];
    float s  = v0 + v1 + v2;
    float ss = fmaf(v0, v0, fmaf(v1, v1, v2 * v2));
    #pragma unroll
    for (int o = 16; o; o >>= 1) {
        s  += __shfl_xor_sync(0xffffffffu, s,  o);
        ss += __shfl_xor_sync(0xffffffffu, ss, o);
    }
    if ((tid & 31) == 0) { red[0][tid >> 5] = s; red[1][tid >> 5] = ss; }
    __syncthreads();
    if (tid < 32) {
        float a = (tid < 8) ? red[0][tid] : 0.f;
        float c = (tid < 8) ? red[1][tid] : 0.f;
        #pragma unroll
        for (int o = 4; o; o >>= 1) {
            a += __shfl_xor_sync(0xffffffffu, a, o);
            c += __shfl_xor_sync(0xffffffffu, c, o);
        }
        if (tid == 0) { red[0][0] = a; red[1][0] = c; }
    }
    __syncthreads();
    float mu  = red[0][0] * (1.0f / DIM);
    float var = red[1][0] * (1.0f / DIM) - mu * mu;
    float r = rsqrtf(var + 1e-5f);
    float* orow = out + (size_t)row * DIM;
    orow[tid]       = (v0 - mu) * r * gw[tid]       + bw[tid];
    orow[tid + 256] = (v1 - mu) * r * gw[tid + 256] + bw[tid + 256];
    orow[tid + 512] = (v2 - mu) * r * gw[tid + 512] + bw[tid + 512];
}

// -------- SGEMM 128x128x8, f32x2 inner loop, fused epilogues ----------------
// EPI: 0 = +bias, 1 = +bias +residual, 2 = +bias then exact GELU
template<int EPI>
__global__ void __launch_bounds__(256) gemm_kernel(
    const float* __restrict__ A, const float* __restrict__ W,
    const float* __restrict__ bias, const float* __restrict__ res,
    float* __restrict__ C, int M, int N, int K)
{
    __shared__ __align__(16) float As[8][128];
    __shared__ __align__(16) float Bs[8][128];
    int tid = threadIdx.x;
    int tx = tid & 15, ty = tid >> 4;
    int m0 = blockIdx.y << 7, n0 = blockIdx.x << 7;
    int arow = tid >> 1, acg = tid & 1;
    int brow = tid >> 5, bc4 = tid & 31;
    const float* Ap = A + (size_t)(m0 + arow) * K + acg * 4;
    const float* Wp = W + (size_t)brow * N + n0 + bc4 * 4;
    float4 af = *(const float4*)Ap;
    float4 bf = *(const float4*)Wp;
    ull acc[8][4];
    #pragma unroll
    for (int i = 0; i < 8; i++)
        #pragma unroll
        for (int j = 0; j < 4; j++) acc[i][j] = 0ull;

    int T = K >> 3;
    for (int t = 0; t < T; t++) {
        As[acg * 4 + 0][arow] = af.x;
        As[acg * 4 + 1][arow] = af.y;
        As[acg * 4 + 2][arow] = af.z;
        As[acg * 4 + 3][arow] = af.w;
        *(float4*)&Bs[brow][bc4 * 4] = bf;
        __syncthreads();
        if (t + 1 < T) {
            af = *(const float4*)(Ap + (t + 1) * 8);
            bf = *(const float4*)(Wp + (size_t)(t + 1) * 8 * N);
        }
        #pragma unroll
        for (int k = 0; k < 8; k++) {
            float4 a0 = *(const float4*)&As[k][ty * 4];
            float4 a1 = *(const float4*)&As[k][64 + ty * 4];
            ulonglong2 b0 = *(const ulonglong2*)&Bs[k][tx * 4];
            ulonglong2 b1 = *(const ulonglong2*)&Bs[k][64 + tx * 4];
#define GEMM_ROW(i, aval) { ull pa = pack2(aval); \
            fma2(acc[i][0], pa, b0.x); fma2(acc[i][1], pa, b0.y); \
            fma2(acc[i][2], pa, b1.x); fma2(acc[i][3], pa, b1.y); }
            GEMM_ROW(0, a0.x) GEMM_ROW(1, a0.y) GEMM_ROW(2, a0.z) GEMM_ROW(3, a0.w)
            GEMM_ROW(4, a1.x) GEMM_ROW(5, a1.y) GEMM_ROW(6, a1.z) GEMM_ROW(7, a1.w)
#undef GEMM_ROW
        }
        __syncthreads();
    }
    #pragma unroll
    for (int i = 0; i < 8; i++) {
        int row = m0 + ((i < 4) ? (ty * 4 + i) : (64 + ty * 4 + i - 4));
        float* crow = C + (size_t)row * N;
        const float* rrow = (EPI == 1) ? (res + (size_t)row * N) : (const float*)0;
        #pragma unroll
        for (int j = 0; j < 4; j++) {
            int col = n0 + ((j < 2) ? (tx * 4 + 2 * j) : (64 + tx * 4 + 2 * (j - 2)));
            float2 v = unpack2(acc[i][j]);
            v.x += bias[col]; v.y += bias[col + 1];
            if (EPI == 1) { v.x += rrow[col]; v.y += rrow[col + 1]; }
            if (EPI == 2) { v.x = gelu_f(v.x); v.y = gelu_f(v.y); }
            *(float2*)&crow[col] = v;
        }
    }
}

// -------- fused attention: 128-query tile, flash-style online softmax -------
#define QTS 128
#define KTS 64
#define QST 132
#define KST 68
#define ATTN_SMEM ((64 * QST + 64 * KST + 64 * KST + 64 * QST) * 4)

__global__ void __launch_bounds__(256) attn_kernel(const float* __restrict__ qkv,
                                                   float* __restrict__ out)
{
    extern __shared__ float smraw[];
    float* Qt = smraw;               // [64][QST]  Q transposed (d-major), pre-scaled
    float* Kt = Qt + 64 * QST;       // [64][KST]  K transposed (d-major)
    float* Vs = Kt + 64 * KST;       // [64][KST]  V (key-major)
    float* Pt = Vs + 64 * KST;       // [64][QST]  probs transposed (key-major)

    int bh = blockIdx.x;
    int b = bh / HEADS, h = bh - b * HEADS;
    int q0 = blockIdx.y * QTS;
    int tid = threadIdx.x;
    int tx = tid & 15, ty = tid >> 4;
    const float* base = qkv + (size_t)b * N_SEQ * (3 * DIM) + h * HD;

    for (int i = tid; i < QTS * HD; i += 256) {
        int r = i >> 6, d = i & 63;
        Qt[d * QST + r] = base[(size_t)(q0 + r) * (3 * DIM) + d] * 0.125f;
    }

    ull o[4][4];
    float m[8], l[8];
    #pragma unroll
    for (int i = 0; i < 4; i++)
        #pragma unroll
        for (int j = 0; j < 4; j++) o[i][j] = 0ull;
    #pragma unroll
    for (int i = 0; i < 8; i++) { m[i] = -1e30f; l[i] = 0.f; }

    for (int t = 0; t < N_SEQ / KTS; t++) {
        __syncthreads();
        for (int i = tid; i < KTS * HD; i += 256) {
            int r = i >> 6, d = i & 63;
            const float* kr = base + (size_t)(t * KTS + r) * (3 * DIM);
            Kt[d * KST + r] = kr[DIM + d];
            Vs[r * KST + d] = kr[2 * DIM + d];
        }
        __syncthreads();

        // scores S[128][64] = Qs @ K^T (rows packed in pairs)
        ull s2[4][4];
        #pragma unroll
        for (int i = 0; i < 4; i++)
            #pragma unroll
            for (int j = 0; j < 4; j++) s2[i][j] = 0ull;
        #pragma unroll 4
        for (int d = 0; d < HD; d++) {
            const float* q = Qt + d * QST;
            ulonglong2 a0 = *(const ulonglong2*)(q + ty * 4);
            ulonglong2 a1 = *(const ulonglong2*)(q + 64 + ty * 4);
            const float* kd = Kt + d * KST;
#define SC_COL(j, kval) { ull pb = pack2(kval); \
            fma2(s2[0][j], a0.x, pb); fma2(s2[1][j], a0.y, pb); \
            fma2(s2[2][j], a1.x, pb); fma2(s2[3][j], a1.y, pb); }
            SC_COL(0, kd[tx]) SC_COL(1, kd[tx + 16]) SC_COL(2, kd[tx + 32]) SC_COL(3, kd[tx + 48])
#undef SC_COL
        }

        // online softmax per row-pair; probs -> Pt (transposed)
        #pragma unroll
        for (int rp = 0; rp < 4; rp++) {
            float2 s0 = unpack2(s2[rp][0]);
            float2 s1 = unpack2(s2[rp][1]);
            float2 sc = unpack2(s2[rp][2]);
            float2 s3 = unpack2(s2[rp][3]);
            float me = fmaxf(fmaxf(s0.x, s1.x), fmaxf(sc.x, s3.x));
            float mo = fmaxf(fmaxf(s0.y, s1.y), fmaxf(sc.y, s3.y));
            #pragma unroll
            for (int ofs = 8; ofs; ofs >>= 1) {
                me = fmaxf(me, __shfl_xor_sync(0xffffffffu, me, ofs));
                mo = fmaxf(mo, __shfl_xor_sync(0xffffffffu, mo, ofs));
            }
            int re = 2 * rp, ro = re + 1;
            float mne = fmaxf(m[re], me), mno = fmaxf(m[ro], mo);
            float ce = __expf(m[re] - mne), co = __expf(m[ro] - mno);
            float p0e = __expf(s0.x - mne), p1e = __expf(s1.x - mne);
            float p2e = __expf(sc.x - mne), p3e = __expf(s3.x - mne);
            float p0o = __expf(s0.y - mno), p1o = __expf(s1.y - mno);
            float p2o = __expf(sc.y - mno), p3o = __expf(s3.y - mno);
            float lse = (p0e + p1e) + (p2e + p3e);
            float lso = (p0o + p1o) + (p2o + p3o);
            #pragma unroll
            for (int ofs = 8; ofs; ofs >>= 1) {
                lse += __shfl_xor_sync(0xffffffffu, lse, ofs);
                lso += __shfl_xor_sync(0xffffffffu, lso, ofs);
            }
            l[re] = l[re] * ce + lse;
            l[ro] = l[ro] * co + lso;
            m[re] = mne; m[ro] = mno;
            ull cc = pack2(ce, co);
            mul2(o[rp][0], cc); mul2(o[rp][1], cc); mul2(o[rp][2], cc); mul2(o[rp][3], cc);
            int rbase = (rp < 2) ? (ty * 4 + 2 * rp) : (64 + ty * 4 + 2 * (rp - 2));
            *(float2*)(Pt + (tx     ) * QST + rbase) = make_float2(p0e, p0o);
            *(float2*)(Pt + (tx + 16) * QST + rbase) = make_float2(p1e, p1o);
            *(float2*)(Pt + (tx + 32) * QST + rbase) = make_float2(p2e, p2o);
            *(float2*)(Pt + (tx + 48) * QST + rbase) = make_float2(p3e, p3o);
        }
        __syncthreads();

        // ctx accumulate O[128][64] += P @ V
        #pragma unroll 4
        for (int k = 0; k < KTS; k++) {
            const float* pr = Pt + k * QST;
            ulonglong2 p0 = *(const ulonglong2*)(pr + ty * 4);
            ulonglong2 p1 = *(const ulonglong2*)(pr + 64 + ty * 4);
            const float* vr = Vs + k * KST;
#define CT_COL(j, vval) { ull pb = pack2(vval); \
            fma2(o[0][j], p0.x, pb); fma2(o[1][j], p0.y, pb); \
            fma2(o[2][j], p1.x, pb); fma2(o[3][j], p1.y, pb); }
            CT_COL(0, vr[tx]) CT_COL(1, vr[tx + 16]) CT_COL(2, vr[tx + 32]) CT_COL(3, vr[tx + 48])
#undef CT_COL
        }
    }

    // normalize + write ctx in [B, N, DIM] layout
    #pragma unroll
    for (int rp = 0; rp < 4; rp++) {
        int rbase = (rp < 2) ? (ty * 4 + 2 * rp) : (64 + ty * 4 + 2 * (rp - 2));
        float ie = 1.0f / l[2 * rp], io = 1.0f / l[2 * rp + 1];
        float* oe = out + ((size_t)b * N_SEQ + q0 + rbase) * DIM + h * HD;
        float* oo = oe + DIM;
        float2 v;
        v = unpack2(o[rp][0]); oe[tx]      = v.x * ie; oo[tx]      = v.y * io;
        v = unpack2(o[rp][1]); oe[tx + 16] = v.x * ie; oo[tx + 16] = v.y * io;
        v = unpack2(o[rp][2]); oe[tx + 32] = v.x * ie; oo[tx + 32] = v.y * io;
        v = unpack2(o[rp][3]); oe[tx + 48] = v.x * ie; oo[tx + 48] = v.y * io;
    }
}

// ---------------- launch ----------------------------------------------------
extern "C" void kernel_launch(void* const* d_in, const int* in_sizes, int n_in,
                              void* d_out, int out_size)
{
    const float* x      = (const float*)d_in[0];
    const float* ln1_g  = (const float*)d_in[1];
    const float* ln1_b  = (const float*)d_in[2];
    const float* qkv_w  = (const float*)d_in[3];
    const float* qkv_b  = (const float*)d_in[4];
    const float* proj_w = (const float*)d_in[5];
    const float* proj_b = (const float*)d_in[6];
    const float* ln2_g  = (const float*)d_in[7];
    const float* ln2_b  = (const float*)d_in[8];
    const float* fc1_w  = (const float*)d_in[9];
    const float* fc1_b  = (const float*)d_in[10];
    const float* fc2_w  = (const float*)d_in[11];
    const float* fc2_b  = (const float*)d_in[12];
    const float* ln3_g  = (const float*)d_in[13];
    const float* ln3_b  = (const float*)d_in[14];
    float* out = (float*)d_out;

    float *xn1, *qkv, *ctx, *xa, *ffin, *hbuf, *xm;
    cudaGetSymbolAddress((void**)&xn1,  g_xn1);
    cudaGetSymbolAddress((void**)&qkv,  g_qkv);
    cudaGetSymbolAddress((void**)&ctx,  g_ctx);
    cudaGetSymbolAddress((void**)&xa,   g_xa);
    cudaGetSymbolAddress((void**)&ffin, g_ffin);
    cudaGetSymbolAddress((void**)&hbuf, g_h);
    cudaGetSymbolAddress((void**)&xm,   g_xm);

    static int smem_set = 0;
    if (!smem_set) {
        cudaFuncSetAttribute(attn_kernel, cudaFuncAttributeMaxDynamicSharedMemorySize, ATTN_SMEM);
        smem_set = 1;
    }

    ln_kernel<<<TOK, 256>>>(x, ln1_g, ln1_b, xn1);
    gemm_kernel<0><<<dim3(3 * DIM / 128, TOK / 128), 256>>>(xn1, qkv_w, qkv_b, nullptr, qkv, TOK, 3 * DIM, DIM);
    attn_kernel<<<dim3(BATCH * HEADS, N_SEQ / QTS), 256, ATTN_SMEM>>>(qkv, ctx);
    gemm_kernel<1><<<dim3(DIM / 128, TOK / 128), 256>>>(ctx, proj_w, proj_b, x, xa, TOK, DIM, DIM);
    ln_kernel<<<TOK, 256>>>(xa, ln2_g, ln2_b, ffin);
    gemm_kernel<2><<<dim3(HIDDEN / 128, TOK / 128), 256>>>(ffin, fc1_w, fc1_b, nullptr, hbuf, TOK, HIDDEN, DIM);
    gemm_kernel<1><<<dim3(DIM / 128, TOK / 128), 256>>>(hbuf, fc2_w, fc2_b, ffin, xm, TOK, DIM, HIDDEN);
    ln_kernel<<<TOK, 256>>>(xm, ln3_g, ln3_b, out);
}

// round 13
// speedup vs baseline: 1.5713x; 1.5713x over previous
#include <cuda_runtime.h>
#include <cuda_bf16.h>
#include <stdint.h>
#include <cstdint>
#include <math.h>

#define DIM 768
#define HEADS 12
#define HD 64
#define HIDDEN 3072
#define BATCH 16
#define N_SEQ 1024
#define TOK (BATCH * N_SEQ)

typedef unsigned long long ull;

// ---------------- scratch (__device__ globals; no allocs allowed) -----------
__device__ float g_xn1[(size_t)TOK * DIM];
__device__ float g_qkv[(size_t)TOK * 3 * DIM];
__device__ float g_ctx[(size_t)TOK * DIM];
__device__ float g_xa[(size_t)TOK * DIM];
__device__ float g_ffin[(size_t)TOK * DIM];
__device__ float g_h[(size_t)TOK * HIDDEN];
__device__ float g_xm[(size_t)TOK * DIM];
// K-concat split activation buffer (reused per GEMM): [M, 3K], max K=HIDDEN
__device__ __align__(256) __nv_bfloat16 g_aext[(size_t)TOK * 3 * HIDDEN];
// K-concat split weights, transposed: [N, 3K] = [Bh | Bl | Bh]
__device__ __align__(256) __nv_bfloat16 g_wqkv_e[(size_t)(3 * DIM) * 3 * DIM];
__device__ __align__(256) __nv_bfloat16 g_wproj_e[(size_t)DIM * 3 * DIM];
__device__ __align__(256) __nv_bfloat16 g_wfc1_e[(size_t)HIDDEN * 3 * DIM];
__device__ __align__(256) __nv_bfloat16 g_wfc2_e[(size_t)DIM * 3 * HIDDEN];

// ---------------- helpers ----------------------------------------------------
__device__ __forceinline__ uint32_t smem_u32(const void* p) {
    uint32_t a;
    asm("{ .reg .u64 t; cvta.to.shared.u64 t, %1; cvt.u32.u64 %0, t; }" : "=r"(a) : "l"(p));
    return a;
}
__device__ __forceinline__ void cp16(uint32_t s, const void* g) {
    asm volatile("cp.async.cg.shared.global [%0], [%1], 16;" :: "r"(s), "l"(g));
}
#define CP_COMMIT() asm volatile("cp.async.commit_group;" ::: "memory")
#define CP_WAIT0()  asm volatile("cp.async.wait_group 0;" ::: "memory")

__device__ __forceinline__ ull pack2(float x) {
    ull r; asm("mov.b64 %0, {%1, %1};" : "=l"(r) : "f"(x)); return r;
}
__device__ __forceinline__ ull pack2(float x, float y) {
    ull r; asm("mov.b64 %0, {%1, %2};" : "=l"(r) : "f"(x), "f"(y)); return r;
}
__device__ __forceinline__ float2 unpack2(ull v) {
    float2 f; asm("mov.b64 {%0, %1}, %2;" : "=f"(f.x), "=f"(f.y) : "l"(v)); return f;
}
__device__ __forceinline__ void fma2(ull& c, ull a, ull b) {
    asm("fma.rn.f32x2 %0, %1, %2, %0;" : "+l"(c) : "l"(a), "l"(b));
}
__device__ __forceinline__ void mul2(ull& c, ull a) {
    asm("mul.rn.f32x2 %0, %0, %1;" : "+l"(c) : "l"(a));
}
__device__ __forceinline__ float gelu_f(float x) {
    return 0.5f * x * (1.0f + erff(x * 0.70710678118654752440f));
}

// ---------------- weight prep: W[K,N] f32 -> Bext[N,3K] = [Bh|Bl|Bh] --------
__global__ void __launch_bounds__(1024) wsplit_ext_kernel(const float* __restrict__ W,
                                                          __nv_bfloat16* __restrict__ Bext,
                                                          int K, int N)
{
    __shared__ float tile[32][33];
    int k0 = blockIdx.y * 32, n0 = blockIdx.x * 32;
    tile[threadIdx.y][threadIdx.x] = W[(size_t)(k0 + threadIdx.y) * N + n0 + threadIdx.x];
    __syncthreads();
    float v = tile[threadIdx.x][threadIdx.y];          // = W[k0+tx][n0+ty]
    __nv_bfloat16 h = __float2bfloat16(v);
    __nv_bfloat16 l = __float2bfloat16(v - __bfloat162float(h));
    size_t base = (size_t)(n0 + threadIdx.y) * (3 * K) + (k0 + threadIdx.x);
    Bext[base]         = h;
    Bext[base + K]     = l;
    Bext[base + 2 * K] = h;
}

// ---------------- activation prep: A[M,K] f32 -> Aext[M,3K] = [Ah|Ah|Al] ----
__global__ void __launch_bounds__(256) asplit_kernel(const float* __restrict__ A,
                                                     __nv_bfloat16* __restrict__ Aext,
                                                     int K, int total4)
{
    int idx = blockIdx.x * 256 + threadIdx.x;
    if (idx >= total4) return;
    int K4 = K >> 2;
    int row = idx / K4;
    int c = (idx - row * K4) * 4;
    float4 v = *(const float4*)(A + (size_t)row * K + c);
    __nv_bfloat162 h01 = __floats2bfloat162_rn(v.x, v.y);
    __nv_bfloat162 h23 = __floats2bfloat162_rn(v.z, v.w);
    float rx = v.x - __bfloat162float(__low2bfloat16(h01));
    float ry = v.y - __bfloat162float(__high2bfloat16(h01));
    float rz = v.z - __bfloat162float(__low2bfloat16(h23));
    float rw = v.w - __bfloat162float(__high2bfloat16(h23));
    __nv_bfloat162 l01 = __floats2bfloat162_rn(rx, ry);
    __nv_bfloat162 l23 = __floats2bfloat162_rn(rz, rw);
    uint2 hi = make_uint2(*(uint32_t*)&h01, *(uint32_t*)&h23);
    uint2 lo = make_uint2(*(uint32_t*)&l01, *(uint32_t*)&l23);
    size_t b = (size_t)row * (3 * K) + c;
    *(uint2*)(Aext + b)         = hi;
    *(uint2*)(Aext + b + K)     = hi;
    *(uint2*)(Aext + b + 2 * K) = lo;
}

// ---------------- LayerNorm: one 256-thread block per token row -------------
__global__ void __launch_bounds__(256) ln_kernel(const float* __restrict__ x,
                                                 const float* __restrict__ gw,
                                                 const float* __restrict__ bw,
                                                 float* __restrict__ out)
{
    __shared__ float red[2][8];
    int row = blockIdx.x, tid = threadIdx.x;
    const float* xr = x + (size_t)row * DIM;
    float v0 = xr[tid], v1 = xr[tid + 256], v2 = xr[tid + 512];
    float s  = v0 + v1 + v2;
    float ss = fmaf(v0, v0, fmaf(v1, v1, v2 * v2));
    #pragma unroll
    for (int o = 16; o; o >>= 1) {
        s  += __shfl_xor_sync(0xffffffffu, s,  o);
        ss += __shfl_xor_sync(0xffffffffu, ss, o);
    }
    if ((tid & 31) == 0) { red[0][tid >> 5] = s; red[1][tid >> 5] = ss; }
    __syncthreads();
    if (tid < 32) {
        float a = (tid < 8) ? red[0][tid] : 0.f;
        float c = (tid < 8) ? red[1][tid] : 0.f;
        #pragma unroll
        for (int o = 4; o; o >>= 1) {
            a += __shfl_xor_sync(0xffffffffu, a, o);
            c += __shfl_xor_sync(0xffffffffu, c, o);
        }
        if (tid == 0) { red[0][0] = a; red[1][0] = c; }
    }
    __syncthreads();
    float mu  = red[0][0] * (1.0f / DIM);
    float var = red[1][0] * (1.0f / DIM) - mu * mu;
    float r = rsqrtf(var + 1e-5f);
    float* orow = out + (size_t)row * DIM;
    orow[tid]       = (v0 - mu) * r * gw[tid]       + bw[tid];
    orow[tid + 256] = (v1 - mu) * r * gw[tid + 256] + bw[tid + 256];
    orow[tid + 512] = (v2 - mu) * r * gw[tid + 512] + bw[tid + 512];
}

// ---------------- HMMA GEMM: C[M,N] = Aext[M,Kext] @ Bext[N,Kext]^T ---------
// 128x128 CTA tile, BK=32, 8 warps (2M x 4N), warp tile 64x32, m16n8k16 bf16.
// EPI: 0=+bias, 1=+bias+res, 2=+bias,GELU
#define BM 128
#define BN 128
#define BK 32
#define ASTR 40   // bf16 per smem row (80 B): 16B-aligned, conflict-free ldmatrix

__device__ __forceinline__ void gtile_issue(const __nv_bfloat16* ga,
                                            const __nv_bfloat16* gb,
                                            size_t Kext, uint32_t sA, uint32_t sB, int tid)
{
    #pragma unroll
    for (int i = 0; i < 2; i++) {
        int c = tid + i * 256;       // 512 chunks of 16 B per tile
        int r = c >> 2, cc = c & 3;
        uint32_t off = (uint32_t)((r * ASTR + cc * 8) * 2);
        cp16(sA + off, ga + (size_t)r * Kext + cc * 8);
        cp16(sB + off, gb + (size_t)r * Kext + cc * 8);
    }
}

template<int EPI>
__global__ __launch_bounds__(256, 2)
void gemm_mma(const __nv_bfloat16* __restrict__ A, const __nv_bfloat16* __restrict__ B,
              const float* __restrict__ bias, const float* __restrict__ res,
              float* __restrict__ C, int M, int N, int Kext)
{
    __shared__ __align__(16) __nv_bfloat16 smA[2][BM * ASTR];
    __shared__ __align__(16) __nv_bfloat16 smB[2][BN * ASTR];

    int tid = threadIdx.x, lane = tid & 31, wid = tid >> 5;
    int wm = wid & 1, wn = wid >> 1;
    int m0 = blockIdx.y * BM, n0 = blockIdx.x * BN;

    float acc[4][4][4];
    #pragma unroll
    for (int i = 0; i < 4; i++)
        #pragma unroll
        for (int j = 0; j < 4; j++)
            #pragma unroll
            for (int k = 0; k < 4; k++) acc[i][j][k] = 0.f;

    const __nv_bfloat16* gA = A + (size_t)m0 * Kext;
    const __nv_bfloat16* gB = B + (size_t)n0 * Kext;

    // ldmatrix per-lane base offsets (bytes)
    uint32_t a_off = (uint32_t)(((wm * 64 + (lane & 15)) * ASTR + ((lane >> 4) & 1) * 8) * 2);
    int bn = ((lane >> 4) & 1) * 8 + (lane & 7);
    int bk = ((lane >> 3) & 1) * 8;
    uint32_t b_off = (uint32_t)(((wn * 32 + bn) * ASTR + bk) * 2);

    int T = Kext / BK;
    gtile_issue(gA, gB, Kext, smem_u32(&smA[0][0]), smem_u32(&smB[0][0]), tid);
    CP_COMMIT();

    for (int t = 0; t < T; t++) {
        CP_WAIT0();
        __syncthreads();
        if (t + 1 < T) {
            int ns = (t + 1) & 1;
            gtile_issue(gA + (size_t)(t + 1) * BK, gB + (size_t)(t + 1) * BK, Kext,
                        smem_u32(&smA[ns][0]), smem_u32(&smB[ns][0]), tid);
            CP_COMMIT();
        }
        int s = t & 1;
        uint32_t sA = smem_u32(&smA[s][0]);
        uint32_t sB = smem_u32(&smB[s][0]);
        #pragma unroll
        for (int k16 = 0; k16 < 2; k16++) {
            uint32_t a[4][4];
            #pragma unroll
            for (int mf = 0; mf < 4; mf++) {
                uint32_t ad = sA + a_off + (uint32_t)(mf * 16 * ASTR * 2 + k16 * 32);
                asm volatile("ldmatrix.sync.aligned.m8n8.x4.shared.b16 {%0,%1,%2,%3}, [%4];"
                    : "=r"(a[mf][0]), "=r"(a[mf][1]), "=r"(a[mf][2]), "=r"(a[mf][3]) : "r"(ad));
            }
            uint32_t b[4][2];
            #pragma unroll
            for (int p = 0; p < 2; p++) {
                uint32_t bd = sB + b_off + (uint32_t)(p * 16 * ASTR * 2 + k16 * 32);
                asm volatile("ldmatrix.sync.aligned.m8n8.x4.shared.b16 {%0,%1,%2,%3}, [%4];"
                    : "=r"(b[2*p][0]), "=r"(b[2*p][1]), "=r"(b[2*p+1][0]), "=r"(b[2*p+1][1]) : "r"(bd));
            }
            #pragma unroll
            for (int mf = 0; mf < 4; mf++)
                #pragma unroll
                for (int nf = 0; nf < 4; nf++) {
                    asm volatile(
                        "mma.sync.aligned.m16n8k16.row.col.f32.bf16.bf16.f32 "
                        "{%0,%1,%2,%3}, {%4,%5,%6,%7}, {%8,%9}, {%0,%1,%2,%3};"
                        : "+f"(acc[mf][nf][0]), "+f"(acc[mf][nf][1]),
                          "+f"(acc[mf][nf][2]), "+f"(acc[mf][nf][3])
                        : "r"(a[mf][0]), "r"(a[mf][1]), "r"(a[mf][2]), "r"(a[mf][3]),
                          "r"(b[nf][0]), "r"(b[nf][1]));
                }
        }
        __syncthreads();
    }

    // epilogue
    int g = lane >> 2, tg = lane & 3;
    #pragma unroll
    for (int mf = 0; mf < 4; mf++) {
        int row = m0 + wm * 64 + mf * 16 + g;
        #pragma unroll
        for (int nf = 0; nf < 4; nf++) {
            int col = n0 + wn * 32 + nf * 8 + tg * 2;
            float bx = bias[col], by = bias[col + 1];
            float2 v0 = make_float2(acc[mf][nf][0] + bx, acc[mf][nf][1] + by);
            float2 v1 = make_float2(acc[mf][nf][2] + bx, acc[mf][nf][3] + by);
            if (EPI == 1) {
                const float* r0 = res + (size_t)row * N + col;
                const float* r1 = res + (size_t)(row + 8) * N + col;
                v0.x += r0[0]; v0.y += r0[1];
                v1.x += r1[0]; v1.y += r1[1];
            }
            if (EPI == 2) {
                v0.x = gelu_f(v0.x); v0.y = gelu_f(v0.y);
                v1.x = gelu_f(v1.x); v1.y = gelu_f(v1.y);
            }
            *(float2*)(C + (size_t)row * N + col)       = v0;
            *(float2*)(C + (size_t)(row + 8) * N + col) = v1;
        }
    }
}

// -------- fused attention: 128-query tile, flash-style (unchanged, proven) --
#define QTS 128
#define KTS 64
#define QST 132
#define KST 68
#define ATTN_SMEM ((64 * QST + 64 * KST + 64 * KST + 64 * QST) * 4)

__global__ void __launch_bounds__(256) attn_kernel(const float* __restrict__ qkv,
                                                   float* __restrict__ out)
{
    extern __shared__ float smraw[];
    float* Qt = smraw;
    float* Kt = Qt + 64 * QST;
    float* Vs = Kt + 64 * KST;
    float* Pt = Vs + 64 * KST;

    int bh = blockIdx.x;
    int b = bh / HEADS, h = bh - b * HEADS;
    int q0 = blockIdx.y * QTS;
    int tid = threadIdx.x;
    int tx = tid & 15, ty = tid >> 4;
    const float* base = qkv + (size_t)b * N_SEQ * (3 * DIM) + h * HD;

    for (int i = tid; i < QTS * HD; i += 256) {
        int r = i >> 6, d = i & 63;
        Qt[d * QST + r] = base[(size_t)(q0 + r) * (3 * DIM) + d] * 0.125f;
    }

    ull o[4][4];
    float m[8], l[8];
    #pragma unroll
    for (int i = 0; i < 4; i++)
        #pragma unroll
        for (int j = 0; j < 4; j++) o[i][j] = 0ull;
    #pragma unroll
    for (int i = 0; i < 8; i++) { m[i] = -1e30f; l[i] = 0.f; }

    for (int t = 0; t < N_SEQ / KTS; t++) {
        __syncthreads();
        for (int i = tid; i < KTS * HD; i += 256) {
            int r = i >> 6, d = i & 63;
            const float* kr = base + (size_t)(t * KTS + r) * (3 * DIM);
            Kt[d * KST + r] = kr[DIM + d];
            Vs[r * KST + d] = kr[2 * DIM + d];
        }
        __syncthreads();

        ull s2[4][4];
        #pragma unroll
        for (int i = 0; i < 4; i++)
            #pragma unroll
            for (int j = 0; j < 4; j++) s2[i][j] = 0ull;
        #pragma unroll 4
        for (int d = 0; d < HD; d++) {
            const float* q = Qt + d * QST;
            ulonglong2 a0 = *(const ulonglong2*)(q + ty * 4);
            ulonglong2 a1 = *(const ulonglong2*)(q + 64 + ty * 4);
            const float* kd = Kt + d * KST;
#define SC_COL(j, kval) { ull pb = pack2(kval); \
            fma2(s2[0][j], a0.x, pb); fma2(s2[1][j], a0.y, pb); \
            fma2(s2[2][j], a1.x, pb); fma2(s2[3][j], a1.y, pb); }
            SC_COL(0, kd[tx]) SC_COL(1, kd[tx + 16]) SC_COL(2, kd[tx + 32]) SC_COL(3, kd[tx + 48])
#undef SC_COL
        }

        #pragma unroll
        for (int rp = 0; rp < 4; rp++) {
            float2 s0 = unpack2(s2[rp][0]);
            float2 s1 = unpack2(s2[rp][1]);
            float2 sc = unpack2(s2[rp][2]);
            float2 s3 = unpack2(s2[rp][3]);
            float me = fmaxf(fmaxf(s0.x, s1.x), fmaxf(sc.x, s3.x));
            float mo = fmaxf(fmaxf(s0.y, s1.y), fmaxf(sc.y, s3.y));
            #pragma unroll
            for (int ofs = 8; ofs; ofs >>= 1) {
                me = fmaxf(me, __shfl_xor_sync(0xffffffffu, me, ofs));
                mo = fmaxf(mo, __shfl_xor_sync(0xffffffffu, mo, ofs));
            }
            int re = 2 * rp, ro = re + 1;
            float mne = fmaxf(m[re], me), mno = fmaxf(m[ro], mo);
            float ce = __expf(m[re] - mne), co = __expf(m[ro] - mno);
            float p0e = __expf(s0.x - mne), p1e = __expf(s1.x - mne);
            float p2e = __expf(sc.x - mne), p3e = __expf(s3.x - mne);
            float p0o = __expf(s0.y - mno), p1o = __expf(s1.y - mno);
            float p2o = __expf(sc.y - mno), p3o = __expf(s3.y - mno);
            float lse = (p0e + p1e) + (p2e + p3e);
            float lso = (p0o + p1o) + (p2o + p3o);
            #pragma unroll
            for (int ofs = 8; ofs; ofs >>= 1) {
                lse += __shfl_xor_sync(0xffffffffu, lse, ofs);
                lso += __shfl_xor_sync(0xffffffffu, lso, ofs);
            }
            l[re] = l[re] * ce + lse;
            l[ro] = l[ro] * co + lso;
            m[re] = mne; m[ro] = mno;
            ull cc = pack2(ce, co);
            mul2(o[rp][0], cc); mul2(o[rp][1], cc); mul2(o[rp][2], cc); mul2(o[rp][3], cc);
            int rbase = (rp < 2) ? (ty * 4 + 2 * rp) : (64 + ty * 4 + 2 * (rp - 2));
            *(float2*)(Pt + (tx     ) * QST + rbase) = make_float2(p0e, p0o);
            *(float2*)(Pt + (tx + 16) * QST + rbase) = make_float2(p1e, p1o);
            *(float2*)(Pt + (tx + 32) * QST + rbase) = make_float2(p2e, p2o);
            *(float2*)(Pt + (tx + 48) * QST + rbase) = make_float2(p3e, p3o);
        }
        __syncthreads();

        #pragma unroll 4
        for (int k = 0; k < KTS; k++) {
            const float* pr = Pt + k * QST;
            ulonglong2 p0 = *(const ulonglong2*)(pr + ty * 4);
            ulonglong2 p1 = *(const ulonglong2*)(pr + 64 + ty * 4);
            const float* vr = Vs + k * KST;
#define CT_COL(j, vval) { ull pb = pack2(vval); \
            fma2(o[0][j], p0.x, pb); fma2(o[1][j], p0.y, pb); \
            fma2(o[2][j], p1.x, pb); fma2(o[3][j], p1.y, pb); }
            CT_COL(0, vr[tx]) CT_COL(1, vr[tx + 16]) CT_COL(2, vr[tx + 32]) CT_COL(3, vr[tx + 48])
#undef CT_COL
        }
    }

    #pragma unroll
    for (int rp = 0; rp < 4; rp++) {
        int rbase = (rp < 2) ? (ty * 4 + 2 * rp) : (64 + ty * 4 + 2 * (rp - 2));
        float ie = 1.0f / l[2 * rp], io = 1.0f / l[2 * rp + 1];
        float* oe = out + ((size_t)b * N_SEQ + q0 + rbase) * DIM + h * HD;
        float* oo = oe + DIM;
        float2 v;
        v = unpack2(o[rp][0]); oe[tx]      = v.x * ie; oo[tx]      = v.y * io;
        v = unpack2(o[rp][1]); oe[tx + 16] = v.x * ie; oo[tx + 16] = v.y * io;
        v = unpack2(o[rp][2]); oe[tx + 32] = v.x * ie; oo[tx + 32] = v.y * io;
        v = unpack2(o[rp][3]); oe[tx + 48] = v.x * ie; oo[tx + 48] = v.y * io;
    }
}

// ---------------- launch ----------------------------------------------------
extern "C" void kernel_launch(void* const* d_in, const int* in_sizes, int n_in,
                              void* d_out, int out_size)
{
    const float* x      = (const float*)d_in[0];
    const float* ln1_g  = (const float*)d_in[1];
    const float* ln1_b  = (const float*)d_in[2];
    const float* qkv_w  = (const float*)d_in[3];
    const float* qkv_b  = (const float*)d_in[4];
    const float* proj_w = (const float*)d_in[5];
    const float* proj_b = (const float*)d_in[6];
    const float* ln2_g  = (const float*)d_in[7];
    const float* ln2_b  = (const float*)d_in[8];
    const float* fc1_w  = (const float*)d_in[9];
    const float* fc1_b  = (const float*)d_in[10];
    const float* fc2_w  = (const float*)d_in[11];
    const float* fc2_b  = (const float*)d_in[12];
    const float* ln3_g  = (const float*)d_in[13];
    const float* ln3_b  = (const float*)d_in[14];
    float* out = (float*)d_out;

    float *xn1, *qkv, *ctx, *xa, *ffin, *hbuf, *xm;
    cudaGetSymbolAddress((void**)&xn1,  g_xn1);
    cudaGetSymbolAddress((void**)&qkv,  g_qkv);
    cudaGetSymbolAddress((void**)&ctx,  g_ctx);
    cudaGetSymbolAddress((void**)&xa,   g_xa);
    cudaGetSymbolAddress((void**)&ffin, g_ffin);
    cudaGetSymbolAddress((void**)&hbuf, g_h);
    cudaGetSymbolAddress((void**)&xm,   g_xm);
    __nv_bfloat16 *aext, *wqe, *wpe, *w1e, *w2e;
    cudaGetSymbolAddress((void**)&aext, g_aext);
    cudaGetSymbolAddress((void**)&wqe, g_wqkv_e);
    cudaGetSymbolAddress((void**)&wpe, g_wproj_e);
    cudaGetSymbolAddress((void**)&w1e, g_wfc1_e);
    cudaGetSymbolAddress((void**)&w2e, g_wfc2_e);

    static int attr_set = 0;
    if (!attr_set) {
        cudaFuncSetAttribute(attn_kernel, cudaFuncAttributeMaxDynamicSharedMemorySize, ATTN_SMEM);
        attr_set = 1;
    }

    // weight prep (re-run every call for determinism; cheap)
    dim3 tb(32, 32);
    wsplit_ext_kernel<<<dim3(3 * DIM / 32, DIM / 32), tb>>>(qkv_w, wqe, DIM, 3 * DIM);
    wsplit_ext_kernel<<<dim3(DIM / 32, DIM / 32), tb>>>(proj_w, wpe, DIM, DIM);
    wsplit_ext_kernel<<<dim3(HIDDEN / 32, DIM / 32), tb>>>(fc1_w, w1e, DIM, HIDDEN);
    wsplit_ext_kernel<<<dim3(DIM / 32, HIDDEN / 32), tb>>>(fc2_w, w2e, HIDDEN, DIM);

    int t4d = TOK * DIM / 4;
    int t4h = TOK * HIDDEN / 4;

    // 1. LN1 + QKV
    ln_kernel<<<TOK, 256>>>(x, ln1_g, ln1_b, xn1);
    asplit_kernel<<<(t4d + 255) / 256, 256>>>(xn1, aext, DIM, t4d);
    gemm_mma<0><<<dim3(3 * DIM / 128, TOK / 128), 256>>>(aext, wqe, qkv_b, nullptr, qkv, TOK, 3 * DIM, 3 * DIM);
    // 2. attention
    attn_kernel<<<dim3(BATCH * HEADS, N_SEQ / QTS), 256, ATTN_SMEM>>>(qkv, ctx);
    // 3. proj + residual
    asplit_kernel<<<(t4d + 255) / 256, 256>>>(ctx, aext, DIM, t4d);
    gemm_mma<1><<<dim3(DIM / 128, TOK / 128), 256>>>(aext, wpe, proj_b, x, xa, TOK, DIM, 3 * DIM);
    // 4. LN2 + MLP
    ln_kernel<<<TOK, 256>>>(xa, ln2_g, ln2_b, ffin);
    asplit_kernel<<<(t4d + 255) / 256, 256>>>(ffin, aext, DIM, t4d);
    gemm_mma<2><<<dim3(HIDDEN / 128, TOK / 128), 256>>>(aext, w1e, fc1_b, nullptr, hbuf, TOK, HIDDEN, 3 * DIM);
    asplit_kernel<<<(t4h + 255) / 256, 256>>>(hbuf, aext, HIDDEN, t4h);
    gemm_mma<1><<<dim3(DIM / 128, TOK / 128), 256>>>(aext, w2e, fc2_b, ffin, xm, TOK, DIM, 3 * HIDDEN);
    // 5. LN3
    ln_kernel<<<TOK, 256>>>(xm, ln3_g, ln3_b, out);
}

// round 14
// speedup vs baseline: 1.9731x; 1.2557x over previous
#include <cuda_runtime.h>
#include <cuda_fp16.h>
#include <stdint.h>
#include <cstdint>
#include <math.h>

#define DIM 768
#define HEADS 12
#define HD 64
#define HIDDEN 3072
#define BATCH 16
#define N_SEQ 1024
#define TOK (BATCH * N_SEQ)

typedef unsigned long long ull;

// ---------------- scratch (__device__ globals; no allocs allowed) -----------
__device__ float g_xn1[(size_t)TOK * DIM];
__device__ float g_qkv[(size_t)TOK * 3 * DIM];
__device__ float g_ctx[(size_t)TOK * DIM];
__device__ float g_xa[(size_t)TOK * DIM];
__device__ float g_ffin[(size_t)TOK * DIM];
__device__ float g_h[(size_t)TOK * HIDDEN];
__device__ float g_xm[(size_t)TOK * DIM];
// K-concat activation buffer (reused per GEMM): [M, 2K] = [Ah | Ah], fp16
__device__ __align__(256) __half g_aext[(size_t)TOK * 2 * HIDDEN];
// K-concat split weights, transposed: [N, 2K] = [Bh | Bl], fp16
__device__ __align__(256) __half g_wqkv_e[(size_t)(3 * DIM) * 2 * DIM];
__device__ __align__(256) __half g_wproj_e[(size_t)DIM * 2 * DIM];
__device__ __align__(256) __half g_wfc1_e[(size_t)HIDDEN * 2 * DIM];
__device__ __align__(256) __half g_wfc2_e[(size_t)DIM * 2 * HIDDEN];

// ---------------- helpers ----------------------------------------------------
__device__ __forceinline__ uint32_t smem_u32(const void* p) {
    uint32_t a;
    asm("{ .reg .u64 t; cvta.to.shared.u64 t, %1; cvt.u32.u64 %0, t; }" : "=r"(a) : "l"(p));
    return a;
}
__device__ __forceinline__ void cp16(uint32_t s, const void* g) {
    asm volatile("cp.async.cg.shared.global [%0], [%1], 16;" :: "r"(s), "l"(g));
}
#define CP_COMMIT() asm volatile("cp.async.commit_group;" ::: "memory")
#define CP_WAIT0()  asm volatile("cp.async.wait_group 0;" ::: "memory")

__device__ __forceinline__ ull pack2(float x) {
    ull r; asm("mov.b64 %0, {%1, %1};" : "=l"(r) : "f"(x)); return r;
}
__device__ __forceinline__ ull pack2(float x, float y) {
    ull r; asm("mov.b64 %0, {%1, %2};" : "=l"(r) : "f"(x), "f"(y)); return r;
}
__device__ __forceinline__ float2 unpack2(ull v) {
    float2 f; asm("mov.b64 {%0, %1}, %2;" : "=f"(f.x), "=f"(f.y) : "l"(v)); return f;
}
__device__ __forceinline__ void fma2(ull& c, ull a, ull b) {
    asm("fma.rn.f32x2 %0, %1, %2, %0;" : "+l"(c) : "l"(a), "l"(b));
}
__device__ __forceinline__ void mul2(ull& c, ull a) {
    asm("mul.rn.f32x2 %0, %0, %1;" : "+l"(c) : "l"(a));
}
__device__ __forceinline__ float gelu_f(float x) {
    return 0.5f * x * (1.0f + erff(x * 0.70710678118654752440f));
}

// ---------------- weight prep: W[K,N] f32 -> Bext[N,2K] = [Bh|Bl] fp16 ------
__global__ void __launch_bounds__(1024) wsplit_ext_kernel(const float* __restrict__ W,
                                                          __half* __restrict__ Bext,
                                                          int K, int N)
{
    __shared__ float tile[32][33];
    int k0 = blockIdx.y * 32, n0 = blockIdx.x * 32;
    tile[threadIdx.y][threadIdx.x] = W[(size_t)(k0 + threadIdx.y) * N + n0 + threadIdx.x];
    __syncthreads();
    float v = tile[threadIdx.x][threadIdx.y];          // = W[k0+tx][n0+ty]
    __half h = __float2half_rn(v);
    __half l = __float2half_rn(v - __half2float(h));
    size_t base = (size_t)(n0 + threadIdx.y) * (2 * K) + (k0 + threadIdx.x);
    Bext[base]     = h;
    Bext[base + K] = l;
}

// ---------------- activation prep: A[M,K] f32 -> Aext[M,2K] = [Ah|Ah] fp16 --
__global__ void __launch_bounds__(256) asplit_kernel(const float* __restrict__ A,
                                                     __half* __restrict__ Aext,
                                                     int K, int total4)
{
    int idx = blockIdx.x * 256 + threadIdx.x;
    if (idx >= total4) return;
    int K4 = K >> 2;
    int row = idx / K4;
    int c = (idx - row * K4) * 4;
    float4 v = *(const float4*)(A + (size_t)row * K + c);
    __half2 h01 = __floats2half2_rn(v.x, v.y);
    __half2 h23 = __floats2half2_rn(v.z, v.w);
    uint2 hi = make_uint2(*(uint32_t*)&h01, *(uint32_t*)&h23);
    size_t b = (size_t)row * (2 * K) + c;
    *(uint2*)(Aext + b)     = hi;
    *(uint2*)(Aext + b + K) = hi;
}

// ---------------- LayerNorm: one 256-thread block per token row -------------
__global__ void __launch_bounds__(256) ln_kernel(const float* __restrict__ x,
                                                 const float* __restrict__ gw,
                                                 const float* __restrict__ bw,
                                                 float* __restrict__ out)
{
    __shared__ float red[2][8];
    int row = blockIdx.x, tid = threadIdx.x;
    const float* xr = x + (size_t)row * DIM;
    float v0 = xr[tid], v1 = xr[tid + 256], v2 = xr[tid + 512];
    float s  = v0 + v1 + v2;
    float ss = fmaf(v0, v0, fmaf(v1, v1, v2 * v2));
    #pragma unroll
    for (int o = 16; o; o >>= 1) {
        s  += __shfl_xor_sync(0xffffffffu, s,  o);
        ss += __shfl_xor_sync(0xffffffffu, ss, o);
    }
    if ((tid & 31) == 0) { red[0][tid >> 5] = s; red[1][tid >> 5] = ss; }
    __syncthreads();
    if (tid < 32) {
        float a = (tid < 8) ? red[0][tid] : 0.f;
        float c = (tid < 8) ? red[1][tid] : 0.f;
        #pragma unroll
        for (int o = 4; o; o >>= 1) {
            a += __shfl_xor_sync(0xffffffffu, a, o);
            c += __shfl_xor_sync(0xffffffffu, c, o);
        }
        if (tid == 0) { red[0][0] = a; red[1][0] = c; }
    }
    __syncthreads();
    float mu  = red[0][0] * (1.0f / DIM);
    float var = red[1][0] * (1.0f / DIM) - mu * mu;
    float r = rsqrtf(var + 1e-5f);
    float* orow = out + (size_t)row * DIM;
    orow[tid]       = (v0 - mu) * r * gw[tid]       + bw[tid];
    orow[tid + 256] = (v1 - mu) * r * gw[tid + 256] + bw[tid + 256];
    orow[tid + 512] = (v2 - mu) * r * gw[tid + 512] + bw[tid + 512];
}

// ---------------- HMMA GEMM: C[M,N] = Aext[M,Kext] @ Bext[N,Kext]^T ---------
// 128x128 CTA tile, BK=32, 8 warps (2M x 4N), warp tile 64x32, m16n8k16 fp16.
// EPI: 0=+bias, 1=+bias+res, 2=+bias,GELU
#define BM 128
#define BN 128
#define BK 32
#define ASTR 40   // fp16 per smem row (80 B): 16B-aligned, conflict-free ldmatrix

__device__ __forceinline__ void gtile_issue(const __half* ga,
                                            const __half* gb,
                                            size_t Kext, uint32_t sA, uint32_t sB, int tid)
{
    #pragma unroll
    for (int i = 0; i < 2; i++) {
        int c = tid + i * 256;       // 512 chunks of 16 B per tile
        int r = c >> 2, cc = c & 3;
        uint32_t off = (uint32_t)((r * ASTR + cc * 8) * 2);
        cp16(sA + off, ga + (size_t)r * Kext + cc * 8);
        cp16(sB + off, gb + (size_t)r * Kext + cc * 8);
    }
}

template<int EPI>
__global__ __launch_bounds__(256, 2)
void gemm_mma(const __half* __restrict__ A, const __half* __restrict__ B,
              const float* __restrict__ bias, const float* __restrict__ res,
              float* __restrict__ C, int M, int N, int Kext)
{
    __shared__ __align__(16) __half smA[2][BM * ASTR];
    __shared__ __align__(16) __half smB[2][BN * ASTR];

    int tid = threadIdx.x, lane = tid & 31, wid = tid >> 5;
    int wm = wid & 1, wn = wid >> 1;
    int m0 = blockIdx.y * BM, n0 = blockIdx.x * BN;

    float acc[4][4][4];
    #pragma unroll
    for (int i = 0; i < 4; i++)
        #pragma unroll
        for (int j = 0; j < 4; j++)
            #pragma unroll
            for (int k = 0; k < 4; k++) acc[i][j][k] = 0.f;

    const __half* gA = A + (size_t)m0 * Kext;
    const __half* gB = B + (size_t)n0 * Kext;

    // ldmatrix per-lane base offsets (bytes)
    uint32_t a_off = (uint32_t)(((wm * 64 + (lane & 15)) * ASTR + ((lane >> 4) & 1) * 8) * 2);
    int bn = ((lane >> 4) & 1) * 8 + (lane & 7);
    int bk = ((lane >> 3) & 1) * 8;
    uint32_t b_off = (uint32_t)(((wn * 32 + bn) * ASTR + bk) * 2);

    int T = Kext / BK;
    gtile_issue(gA, gB, Kext, smem_u32(&smA[0][0]), smem_u32(&smB[0][0]), tid);
    CP_COMMIT();

    for (int t = 0; t < T; t++) {
        CP_WAIT0();
        __syncthreads();
        if (t + 1 < T) {
            int ns = (t + 1) & 1;
            gtile_issue(gA + (size_t)(t + 1) * BK, gB + (size_t)(t + 1) * BK, Kext,
                        smem_u32(&smA[ns][0]), smem_u32(&smB[ns][0]), tid);
            CP_COMMIT();
        }
        int s = t & 1;
        uint32_t sA = smem_u32(&smA[s][0]);
        uint32_t sB = smem_u32(&smB[s][0]);
        #pragma unroll
        for (int k16 = 0; k16 < 2; k16++) {
            uint32_t a[4][4];
            #pragma unroll
            for (int mf = 0; mf < 4; mf++) {
                uint32_t ad = sA + a_off + (uint32_t)(mf * 16 * ASTR * 2 + k16 * 32);
                asm volatile("ldmatrix.sync.aligned.m8n8.x4.shared.b16 {%0,%1,%2,%3}, [%4];"
                    : "=r"(a[mf][0]), "=r"(a[mf][1]), "=r"(a[mf][2]), "=r"(a[mf][3]) : "r"(ad));
            }
            uint32_t b[4][2];
            #pragma unroll
            for (int p = 0; p < 2; p++) {
                uint32_t bd = sB + b_off + (uint32_t)(p * 16 * ASTR * 2 + k16 * 32);
                asm volatile("ldmatrix.sync.aligned.m8n8.x4.shared.b16 {%0,%1,%2,%3}, [%4];"
                    : "=r"(b[2*p][0]), "=r"(b[2*p][1]), "=r"(b[2*p+1][0]), "=r"(b[2*p+1][1]) : "r"(bd));
            }
            #pragma unroll
            for (int mf = 0; mf < 4; mf++)
                #pragma unroll
                for (int nf = 0; nf < 4; nf++) {
                    asm volatile(
                        "mma.sync.aligned.m16n8k16.row.col.f32.f16.f16.f32 "
                        "{%0,%1,%2,%3}, {%4,%5,%6,%7}, {%8,%9}, {%0,%1,%2,%3};"
                        : "+f"(acc[mf][nf][0]), "+f"(acc[mf][nf][1]),
                          "+f"(acc[mf][nf][2]), "+f"(acc[mf][nf][3])
                        : "r"(a[mf][0]), "r"(a[mf][1]), "r"(a[mf][2]), "r"(a[mf][3]),
                          "r"(b[nf][0]), "r"(b[nf][1]));
                }
        }
        __syncthreads();
    }

    // epilogue
    int g = lane >> 2, tg = lane & 3;
    #pragma unroll
    for (int mf = 0; mf < 4; mf++) {
        int row = m0 + wm * 64 + mf * 16 + g;
        #pragma unroll
        for (int nf = 0; nf < 4; nf++) {
            int col = n0 + wn * 32 + nf * 8 + tg * 2;
            float bx = bias[col], by = bias[col + 1];
            float2 v0 = make_float2(acc[mf][nf][0] + bx, acc[mf][nf][1] + by);
            float2 v1 = make_float2(acc[mf][nf][2] + bx, acc[mf][nf][3] + by);
            if (EPI == 1) {
                const float* r0 = res + (size_t)row * N + col;
                const float* r1 = res + (size_t)(row + 8) * N + col;
                v0.x += r0[0]; v0.y += r0[1];
                v1.x += r1[0]; v1.y += r1[1];
            }
            if (EPI == 2) {
                v0.x = gelu_f(v0.x); v0.y = gelu_f(v0.y);
                v1.x = gelu_f(v1.x); v1.y = gelu_f(v1.y);
            }
            *(float2*)(C + (size_t)row * N + col)       = v0;
            *(float2*)(C + (size_t)(row + 8) * N + col) = v1;
        }
    }
}

// -------- fused attention: 128-query tile, flash-style (unchanged, proven) --
#define QTS 128
#define KTS 64
#define QST 132
#define KST 68
#define ATTN_SMEM ((64 * QST + 64 * KST + 64 * KST + 64 * QST) * 4)

__global__ void __launch_bounds__(256) attn_kernel(const float* __restrict__ qkv,
                                                   float* __restrict__ out)
{
    extern __shared__ float smraw[];
    float* Qt = smraw;
    float* Kt = Qt + 64 * QST;
    float* Vs = Kt + 64 * KST;
    float* Pt = Vs + 64 * KST;

    int bh = blockIdx.x;
    int b = bh / HEADS, h = bh - b * HEADS;
    int q0 = blockIdx.y * QTS;
    int tid = threadIdx.x;
    int tx = tid & 15, ty = tid >> 4;
    const float* base = qkv + (size_t)b * N_SEQ * (3 * DIM) + h * HD;

    for (int i = tid; i < QTS * HD; i += 256) {
        int r = i >> 6, d = i & 63;
        Qt[d * QST + r] = base[(size_t)(q0 + r) * (3 * DIM) + d] * 0.125f;
    }

    ull o[4][4];
    float m[8], l[8];
    #pragma unroll
    for (int i = 0; i < 4; i++)
        #pragma unroll
        for (int j = 0; j < 4; j++) o[i][j] = 0ull;
    #pragma unroll
    for (int i = 0; i < 8; i++) { m[i] = -1e30f; l[i] = 0.f; }

    for (int t = 0; t < N_SEQ / KTS; t++) {
        __syncthreads();
        for (int i = tid; i < KTS * HD; i += 256) {
            int r = i >> 6, d = i & 63;
            const float* kr = base + (size_t)(t * KTS + r) * (3 * DIM);
            Kt[d * KST + r] = kr[DIM + d];
            Vs[r * KST + d] = kr[2 * DIM + d];
        }
        __syncthreads();

        ull s2[4][4];
        #pragma unroll
        for (int i = 0; i < 4; i++)
            #pragma unroll
            for (int j = 0; j < 4; j++) s2[i][j] = 0ull;
        #pragma unroll 4
        for (int d = 0; d < HD; d++) {
            const float* q = Qt + d * QST;
            ulonglong2 a0 = *(const ulonglong2*)(q + ty * 4);
            ulonglong2 a1 = *(const ulonglong2*)(q + 64 + ty * 4);
            const float* kd = Kt + d * KST;
#define SC_COL(j, kval) { ull pb = pack2(kval); \
            fma2(s2[0][j], a0.x, pb); fma2(s2[1][j], a0.y, pb); \
            fma2(s2[2][j], a1.x, pb); fma2(s2[3][j], a1.y, pb); }
            SC_COL(0, kd[tx]) SC_COL(1, kd[tx + 16]) SC_COL(2, kd[tx + 32]) SC_COL(3, kd[tx + 48])
#undef SC_COL
        }

        #pragma unroll
        for (int rp = 0; rp < 4; rp++) {
            float2 s0 = unpack2(s2[rp][0]);
            float2 s1 = unpack2(s2[rp][1]);
            float2 sc = unpack2(s2[rp][2]);
            float2 s3 = unpack2(s2[rp][3]);
            float me = fmaxf(fmaxf(s0.x, s1.x), fmaxf(sc.x, s3.x));
            float mo = fmaxf(fmaxf(s0.y, s1.y), fmaxf(sc.y, s3.y));
            #pragma unroll
            for (int ofs = 8; ofs; ofs >>= 1) {
                me = fmaxf(me, __shfl_xor_sync(0xffffffffu, me, ofs));
                mo = fmaxf(mo, __shfl_xor_sync(0xffffffffu, mo, ofs));
            }
            int re = 2 * rp, ro = re + 1;
            float mne = fmaxf(m[re], me), mno = fmaxf(m[ro], mo);
            float ce = __expf(m[re] - mne), co = __expf(m[ro] - mno);
            float p0e = __expf(s0.x - mne), p1e = __expf(s1.x - mne);
            float p2e = __expf(sc.x - mne), p3e = __expf(s3.x - mne);
            float p0o = __expf(s0.y - mno), p1o = __expf(s1.y - mno);
            float p2o = __expf(sc.y - mno), p3o = __expf(s3.y - mno);
            float lse = (p0e + p1e) + (p2e + p3e);
            float lso = (p0o + p1o) + (p2o + p3o);
            #pragma unroll
            for (int ofs = 8; ofs; ofs >>= 1) {
                lse += __shfl_xor_sync(0xffffffffu, lse, ofs);
                lso += __shfl_xor_sync(0xffffffffu, lso, ofs);
            }
            l[re] = l[re] * ce + lse;
            l[ro] = l[ro] * co + lso;
            m[re] = mne; m[ro] = mno;
            ull cc = pack2(ce, co);
            mul2(o[rp][0], cc); mul2(o[rp][1], cc); mul2(o[rp][2], cc); mul2(o[rp][3], cc);
            int rbase = (rp < 2) ? (ty * 4 + 2 * rp) : (64 + ty * 4 + 2 * (rp - 2));
            *(float2*)(Pt + (tx     ) * QST + rbase) = make_float2(p0e, p0o);
            *(float2*)(Pt + (tx + 16) * QST + rbase) = make_float2(p1e, p1o);
            *(float2*)(Pt + (tx + 32) * QST + rbase) = make_float2(p2e, p2o);
            *(float2*)(Pt + (tx + 48) * QST + rbase) = make_float2(p3e, p3o);
        }
        __syncthreads();

        #pragma unroll 4
        for (int k = 0; k < KTS; k++) {
            const float* pr = Pt + k * QST;
            ulonglong2 p0 = *(const ulonglong2*)(pr + ty * 4);
            ulonglong2 p1 = *(const ulonglong2*)(pr + 64 + ty * 4);
            const float* vr = Vs + k * KST;
#define CT_COL(j, vval) { ull pb = pack2(vval); \
            fma2(o[0][j], p0.x, pb); fma2(o[1][j], p0.y, pb); \
            fma2(o[2][j], p1.x, pb); fma2(o[3][j], p1.y, pb); }
            CT_COL(0, vr[tx]) CT_COL(1, vr[tx + 16]) CT_COL(2, vr[tx + 32]) CT_COL(3, vr[tx + 48])
#undef CT_COL
        }
    }

    #pragma unroll
    for (int rp = 0; rp < 4; rp++) {
        int rbase = (rp < 2) ? (ty * 4 + 2 * rp) : (64 + ty * 4 + 2 * (rp - 2));
        float ie = 1.0f / l[2 * rp], io = 1.0f / l[2 * rp + 1];
        float* oe = out + ((size_t)b * N_SEQ + q0 + rbase) * DIM + h * HD;
        float* oo = oe + DIM;
        float2 v;
        v = unpack2(o[rp][0]); oe[tx]      = v.x * ie; oo[tx]      = v.y * io;
        v = unpack2(o[rp][1]); oe[tx + 16] = v.x * ie; oo[tx + 16] = v.y * io;
        v = unpack2(o[rp][2]); oe[tx + 32] = v.x * ie; oo[tx + 32] = v.y * io;
        v = unpack2(o[rp][3]); oe[tx + 48] = v.x * ie; oo[tx + 48] = v.y * io;
    }
}

// ---------------- launch ----------------------------------------------------
extern "C" void kernel_launch(void* const* d_in, const int* in_sizes, int n_in,
                              void* d_out, int out_size)
{
    const float* x      = (const float*)d_in[0];
    const float* ln1_g  = (const float*)d_in[1];
    const float* ln1_b  = (const float*)d_in[2];
    const float* qkv_w  = (const float*)d_in[3];
    const float* qkv_b  = (const float*)d_in[4];
    const float* proj_w = (const float*)d_in[5];
    const float* proj_b = (const float*)d_in[6];
    const float* ln2_g  = (const float*)d_in[7];
    const float* ln2_b  = (const float*)d_in[8];
    const float* fc1_w  = (const float*)d_in[9];
    const float* fc1_b  = (const float*)d_in[10];
    const float* fc2_w  = (const float*)d_in[11];
    const float* fc2_b  = (const float*)d_in[12];
    const float* ln3_g  = (const float*)d_in[13];
    const float* ln3_b  = (const float*)d_in[14];
    float* out = (float*)d_out;

    float *xn1, *qkv, *ctx, *xa, *ffin, *hbuf, *xm;
    cudaGetSymbolAddress((void**)&xn1,  g_xn1);
    cudaGetSymbolAddress((void**)&qkv,  g_qkv);
    cudaGetSymbolAddress((void**)&ctx,  g_ctx);
    cudaGetSymbolAddress((void**)&xa,   g_xa);
    cudaGetSymbolAddress((void**)&ffin, g_ffin);
    cudaGetSymbolAddress((void**)&hbuf, g_h);
    cudaGetSymbolAddress((void**)&xm,   g_xm);
    __half *aext, *wqe, *wpe, *w1e, *w2e;
    cudaGetSymbolAddress((void**)&aext, g_aext);
    cudaGetSymbolAddress((void**)&wqe, g_wqkv_e);
    cudaGetSymbolAddress((void**)&wpe, g_wproj_e);
    cudaGetSymbolAddress((void**)&w1e, g_wfc1_e);
    cudaGetSymbolAddress((void**)&w2e, g_wfc2_e);

    static int attr_set = 0;
    if (!attr_set) {
        cudaFuncSetAttribute(attn_kernel, cudaFuncAttributeMaxDynamicSharedMemorySize, ATTN_SMEM);
        attr_set = 1;
    }

    // weight prep (re-run every call for determinism; cheap)
    dim3 tb(32, 32);
    wsplit_ext_kernel<<<dim3(3 * DIM / 32, DIM / 32), tb>>>(qkv_w, wqe, DIM, 3 * DIM);
    wsplit_ext_kernel<<<dim3(DIM / 32, DIM / 32), tb>>>(proj_w, wpe, DIM, DIM);
    wsplit_ext_kernel<<<dim3(HIDDEN / 32, DIM / 32), tb>>>(fc1_w, w1e, DIM, HIDDEN);
    wsplit_ext_kernel<<<dim3(DIM / 32, HIDDEN / 32), tb>>>(fc2_w, w2e, HIDDEN, DIM);

    int t4d = TOK * DIM / 4;
    int t4h = TOK * HIDDEN / 4;

    // 1. LN1 + QKV
    ln_kernel<<<TOK, 256>>>(x, ln1_g, ln1_b, xn1);
    asplit_kernel<<<(t4d + 255) / 256, 256>>>(xn1, aext, DIM, t4d);
    gemm_mma<0><<<dim3(3 * DIM / 128, TOK / 128), 256>>>(aext, wqe, qkv_b, nullptr, qkv, TOK, 3 * DIM, 2 * DIM);
    // 2. attention
    attn_kernel<<<dim3(BATCH * HEADS, N_SEQ / QTS), 256, ATTN_SMEM>>>(qkv, ctx);
    // 3. proj + residual
    asplit_kernel<<<(t4d + 255) / 256, 256>>>(ctx, aext, DIM, t4d);
    gemm_mma<1><<<dim3(DIM / 128, TOK / 128), 256>>>(aext, wpe, proj_b, x, xa, TOK, DIM, 2 * DIM);
    // 4. LN2 + MLP
    ln_kernel<<<TOK, 256>>>(xa, ln2_g, ln2_b, ffin);
    asplit_kernel<<<(t4d + 255) / 256, 256>>>(ffin, aext, DIM, t4d);
    gemm_mma<2><<<dim3(HIDDEN / 128, TOK / 128), 256>>>(aext, w1e, fc1_b, nullptr, hbuf, TOK, HIDDEN, 2 * DIM);
    asplit_kernel<<<(t4h + 255) / 256, 256>>>(hbuf, aext, HIDDEN, t4h);
    gemm_mma<1><<<dim3(DIM / 128, TOK / 128), 256>>>(aext, w2e, fc2_b, ffin, xm, TOK, DIM, 2 * HIDDEN);
    // 5. LN3
    ln_kernel<<<TOK, 256>>>(xm, ln3_g, ln3_b, out);
}